// round 2
// baseline (speedup 1.0000x reference)
#include <cuda_runtime.h>
#include <cuda_bf16.h>
#include <cstdint>
#include <math.h>

#define Bb 8
#define Ss 2048
#define Ee 2048
#define Hh 16
#define Dd 128
#define PADTOK 50257

// ---------------- scratch (device globals: allocation-free) ----------------
__device__ float g_hs[(size_t)Bb * Ss * Ee];     // normalized hidden states (fp32), 134 MB
__device__ float g_q[Bb * Ee];                   // q rows (rope on q is identity at pos 0)
__device__ float g_sc[Bb * Hh * Ss];             // scores -> attn (softmax in place)
__device__ float g_c[Bb * Hh * Ee];              // c[b,h,:] = sum_s attn * hs
__device__ float g_oattn[Bb * Ee];               // attention output (pre out-proj)
__device__ int   g_ix[Bb];                       // last non-pad index per batch

// ---------------- LayerNorm ----------------
__global__ __launch_bounds__(256) void ln_kernel(const float* __restrict__ x,
                                                 const float* __restrict__ w,
                                                 const float* __restrict__ bias) {
    int row = blockIdx.x;                         // 0 .. B*S-1
    const float4* xin = reinterpret_cast<const float4*>(x + (size_t)row * Ee);
    int tid = threadIdx.x;
    float4 v0 = xin[tid];
    float4 v1 = xin[tid + 256];
    float s  = v0.x + v0.y + v0.z + v0.w + v1.x + v1.y + v1.z + v1.w;
    float s2 = v0.x*v0.x + v0.y*v0.y + v0.z*v0.z + v0.w*v0.w
             + v1.x*v1.x + v1.y*v1.y + v1.z*v1.z + v1.w*v1.w;
    #pragma unroll
    for (int o = 16; o; o >>= 1) {
        s  += __shfl_xor_sync(0xffffffffu, s, o);
        s2 += __shfl_xor_sync(0xffffffffu, s2, o);
    }
    __shared__ float red[16];
    __shared__ float mv[2];
    int warp = tid >> 5, lane = tid & 31;
    if (lane == 0) { red[warp] = s; red[warp + 8] = s2; }
    __syncthreads();
    if (tid == 0) {
        float a = 0.f, b2 = 0.f;
        #pragma unroll
        for (int i = 0; i < 8; i++) { a += red[i]; b2 += red[i + 8]; }
        float mu  = a / (float)Ee;
        float var = b2 / (float)Ee - mu * mu;
        mv[0] = mu; mv[1] = rsqrtf(var + 1e-5f);
    }
    __syncthreads();
    float mu = mv[0], rs = mv[1];
    const float4* wv4 = reinterpret_cast<const float4*>(w);
    const float4* bv4 = reinterpret_cast<const float4*>(bias);
    float4* out = reinterpret_cast<float4*>(g_hs + (size_t)row * Ee);
    {
        float4 wv = wv4[tid], bv = bv4[tid], o;
        o.x = (v0.x - mu) * rs * wv.x + bv.x;
        o.y = (v0.y - mu) * rs * wv.y + bv.y;
        o.z = (v0.z - mu) * rs * wv.z + bv.z;
        o.w = (v0.w - mu) * rs * wv.w + bv.w;
        out[tid] = o;
    }
    {
        float4 wv = wv4[tid + 256], bv = bv4[tid + 256], o;
        o.x = (v1.x - mu) * rs * wv.x + bv.x;
        o.y = (v1.y - mu) * rs * wv.y + bv.y;
        o.z = (v1.z - mu) * rs * wv.z + bv.z;
        o.w = (v1.w - mu) * rs * wv.w + bv.w;
        out[tid + 256] = o;
    }
}

// ---------------- last non-pad index ----------------
__global__ __launch_bounds__(256) void ix_kernel(const int* __restrict__ ids) {
    int b = blockIdx.x;
    int m = -1;
    for (int s = threadIdx.x; s < Ss; s += 256)
        if (ids[b * Ss + s] != PADTOK) m = s;   // s increasing -> last hit = max
    #pragma unroll
    for (int o = 16; o; o >>= 1) m = max(m, __shfl_xor_sync(0xffffffffu, m, o));
    __shared__ int rm[8];
    int warp = threadIdx.x >> 5, lane = threadIdx.x & 31;
    if (lane == 0) rm[warp] = m;
    __syncthreads();
    if (threadIdx.x == 0) {
        int mm = -1;
        #pragma unroll
        for (int i = 0; i < 8; i++) mm = max(mm, rm[i]);
        g_ix[b] = (mm < 0) ? 0 : mm;
    }
}

// ---------------- q = h_last @ q_w.T + q_b  (rope is identity at pos 0) ----------------
__global__ __launch_bounds__(256) void q_kernel(const float* __restrict__ qw,
                                                const float* __restrict__ qb) {
    int b = blockIdx.y;
    int warp = threadIdx.x >> 5, lane = threadIdx.x & 31;
    int j = blockIdx.x * 8 + warp;
    const float4* hrow = reinterpret_cast<const float4*>(g_hs + ((size_t)(b * Ss) + g_ix[b]) * Ee);
    const float4* wrow = reinterpret_cast<const float4*>(qw + (size_t)j * Ee);
    float acc = 0.f;
    #pragma unroll
    for (int it = 0; it < 16; it++) {
        int i4 = it * 32 + lane;
        float4 a = hrow[i4], w = wrow[i4];
        acc += a.x * w.x + a.y * w.y + a.z * w.z + a.w * w.w;
    }
    #pragma unroll
    for (int o = 16; o; o >>= 1) acc += __shfl_xor_sync(0xffffffffu, acc, o);
    if (lane == 0) g_q[b * Ee + j] = acc + qb[j];
}

// ---------------- scores: K GEMM (bf16-split 3xMMA) + rope-on-q epilogue ----------------
__device__ __forceinline__ void mma_bf16(float c[4], uint32_t a0, uint32_t a1, uint32_t a2,
                                         uint32_t a3, uint32_t b0, uint32_t b1) {
    asm volatile(
        "mma.sync.aligned.m16n8k16.row.col.f32.bf16.bf16.f32 "
        "{%0,%1,%2,%3}, {%4,%5,%6,%7}, {%8,%9}, {%0,%1,%2,%3};"
        : "+f"(c[0]), "+f"(c[1]), "+f"(c[2]), "+f"(c[3])
        : "r"(a0), "r"(a1), "r"(a2), "r"(a3), "r"(b0), "r"(b1));
}

__device__ __forceinline__ void splitp(float f0, float f1, uint32_t& hi, uint32_t& lo) {
    __nv_bfloat162 Hv = __floats2bfloat162_rn(f0, f1);     // low = f0, high = f1
    float r0 = f0 - __low2float(Hv);
    float r1 = f1 - __high2float(Hv);
    __nv_bfloat162 Lv = __floats2bfloat162_rn(r0, r1);
    hi = *reinterpret_cast<uint32_t*>(&Hv);
    lo = *reinterpret_cast<uint32_t*>(&Lv);
}

__global__ __launch_bounds__(256) void scores_kernel(const float* __restrict__ kw,
                                                     const float* __restrict__ kb) {
    __shared__ uint32_t AsH[128][17], AsL[128][17], BsH[128][17], BsL[128][17];
    __shared__ float qs[128], kbs[128];
    __shared__ double finv[32];
    __shared__ float red[128][2];

    const int tid = threadIdx.x;
    const int b = blockIdx.z, h = blockIdx.y, s0 = blockIdx.x * 128;
    if (tid < 128) { qs[tid] = g_q[b * Ee + h * Dd + tid]; kbs[tid] = kb[h * Dd + tid]; }
    if (tid < 32) finv[tid] = exp(-((double)(2 * tid) / 64.0) * 9.210340371976184);

    const int warp = tid >> 5, lane = tid & 31;
    const int wm = warp >> 1, wn = warp & 1;
    const int g = lane >> 2, tq = lane & 3;

    float acc[2][8][4];
    #pragma unroll
    for (int i = 0; i < 2; i++)
        #pragma unroll
        for (int j = 0; j < 8; j++)
            #pragma unroll
            for (int k = 0; k < 4; k++) acc[i][j][k] = 0.f;

    const float4* Abase = reinterpret_cast<const float4*>(g_hs + (size_t)(b * Ss + s0) * Ee);
    const float4* Bbase = reinterpret_cast<const float4*>(kw + (size_t)(h * Dd) * Ee);

    for (int k0 = 0; k0 < Ee; k0 += 32) {
        __syncthreads();
        #pragma unroll
        for (int i = 0; i < 4; i++) {
            int idx = tid + i * 256;
            int row = idx >> 3, c4 = idx & 7;
            float4 fa = Abase[row * 512 + (k0 >> 2) + c4];
            uint32_t h0, l0, h1, l1;
            splitp(fa.x, fa.y, h0, l0); splitp(fa.z, fa.w, h1, l1);
            AsH[row][c4 * 2] = h0; AsH[row][c4 * 2 + 1] = h1;
            AsL[row][c4 * 2] = l0; AsL[row][c4 * 2 + 1] = l1;
            float4 fb = Bbase[row * 512 + (k0 >> 2) + c4];
            splitp(fb.x, fb.y, h0, l0); splitp(fb.z, fb.w, h1, l1);
            BsH[row][c4 * 2] = h0; BsH[row][c4 * 2 + 1] = h1;
            BsL[row][c4 * 2] = l0; BsL[row][c4 * 2 + 1] = l1;
        }
        __syncthreads();
        #pragma unroll
        for (int kk2 = 0; kk2 < 16; kk2 += 8) {
            uint32_t aH[2][4], aL[2][4];
            #pragma unroll
            for (int mt = 0; mt < 2; mt++) {
                int r = wm * 32 + mt * 16 + g;
                aH[mt][0] = AsH[r][kk2 + tq];      aH[mt][1] = AsH[r + 8][kk2 + tq];
                aH[mt][2] = AsH[r][kk2 + 4 + tq];  aH[mt][3] = AsH[r + 8][kk2 + 4 + tq];
                aL[mt][0] = AsL[r][kk2 + tq];      aL[mt][1] = AsL[r + 8][kk2 + tq];
                aL[mt][2] = AsL[r][kk2 + 4 + tq];  aL[mt][3] = AsL[r + 8][kk2 + 4 + tq];
            }
            #pragma unroll
            for (int nt = 0; nt < 8; nt++) {
                int n = wn * 64 + nt * 8 + g;
                uint32_t bh0 = BsH[n][kk2 + tq], bh1 = BsH[n][kk2 + 4 + tq];
                uint32_t bl0 = BsL[n][kk2 + tq], bl1 = BsL[n][kk2 + 4 + tq];
                #pragma unroll
                for (int mt = 0; mt < 2; mt++) {
                    mma_bf16(acc[mt][nt], aH[mt][0], aH[mt][1], aH[mt][2], aH[mt][3], bh0, bh1);
                    mma_bf16(acc[mt][nt], aH[mt][0], aH[mt][1], aH[mt][2], aH[mt][3], bl0, bl1);
                    mma_bf16(acc[mt][nt], aL[mt][0], aL[mt][1], aL[mt][2], aL[mt][3], bh0, bh1);
                }
            }
        }
    }
    __syncthreads();

    // epilogue: k += k_b, fold RoPE(pos=s) onto q, dot, reduce
    const double INV2PI = 0.15915494309189535;
    const double TWOPI  = 6.283185307179586;
    #pragma unroll
    for (int mt = 0; mt < 2; mt++) {
        #pragma unroll
        for (int half = 0; half < 2; half++) {
            int rl = wm * 32 + mt * 16 + half * 8 + g;
            int s = s0 + rl;
            float partial = 0.f;
            #pragma unroll
            for (int nt = 0; nt < 8; nt++) {
                int col = wn * 64 + nt * 8 + tq * 2;
                float k0v = acc[mt][nt][half * 2 + 0] + kbs[col];
                float k1v = acc[mt][nt][half * 2 + 1] + kbs[col + 1];
                if (col < 64) {                         // uniform per warp (wn==0)
                    int j = col >> 1;
                    double ang = (double)s * finv[j];
                    double kq = rint(ang * INV2PI);
                    float r = (float)(ang - kq * TWOPI);
                    float sn, cs;
                    __sincosf(r, &sn, &cs);
                    float qe0 = qs[col] * cs + qs[col + 1] * sn;
                    float qe1 = qs[col + 1] * cs - qs[col] * sn;
                    partial += k0v * qe0 + k1v * qe1;
                } else {
                    partial += k0v * qs[col] + k1v * qs[col + 1];
                }
            }
            partial += __shfl_xor_sync(0xffffffffu, partial, 1);
            partial += __shfl_xor_sync(0xffffffffu, partial, 2);
            if (tq == 0) red[rl][wn] = partial;
        }
    }
    __syncthreads();
    if (tid < 128)
        g_sc[(size_t)(b * Hh + h) * Ss + s0 + tid] = red[tid][0] + red[tid][1];
}

// ---------------- softmax over s (per b,h) ----------------
__global__ __launch_bounds__(256) void softmax_kernel() {
    int row = blockIdx.x;                       // b*H + h
    float* p = g_sc + (size_t)row * Ss;
    int tid = threadIdx.x;
    float v[8];
    float m = -1e30f;
    #pragma unroll
    for (int i = 0; i < 8; i++) { v[i] = p[tid + i * 256]; m = fmaxf(m, v[i]); }
    #pragma unroll
    for (int o = 16; o; o >>= 1) m = fmaxf(m, __shfl_xor_sync(0xffffffffu, m, o));
    __shared__ float rs[8];
    int warp = tid >> 5, lane = tid & 31;
    if (lane == 0) rs[warp] = m;
    __syncthreads();
    float mm = rs[0];
    #pragma unroll
    for (int i = 1; i < 8; i++) mm = fmaxf(mm, rs[i]);
    float ssum = 0.f;
    #pragma unroll
    for (int i = 0; i < 8; i++) { v[i] = expf(v[i] - mm); ssum += v[i]; }
    #pragma unroll
    for (int o = 16; o; o >>= 1) ssum += __shfl_xor_sync(0xffffffffu, ssum, o);
    __syncthreads();
    if (lane == 0) rs[warp] = ssum;
    __syncthreads();
    float tot = 0.f;
    #pragma unroll
    for (int i = 0; i < 8; i++) tot += rs[i];
    float inv = 1.f / tot;
    #pragma unroll
    for (int i = 0; i < 8; i++) p[tid + i * 256] = v[i] * inv;
}

// ---------------- c[b,h,e] = sum_s attn * hs ----------------
__global__ void zero_c_kernel() {
    int i = blockIdx.x * blockDim.x + threadIdx.x;
    if (i < Bb * Hh * Ee) g_c[i] = 0.f;
}

__global__ __launch_bounds__(128) void cvec_kernel() {
    __shared__ float at[16][128];
    int tid = threadIdx.x;
    int b = blockIdx.y;
    int e = blockIdx.x * 128 + tid;
    int sbase = blockIdx.z * 256;
    float acc[16];
    #pragma unroll
    for (int i = 0; i < 16; i++) acc[i] = 0.f;
    for (int sc = 0; sc < 256; sc += 128) {
        #pragma unroll
        for (int i = 0; i < 16; i++) {
            int idx = tid + i * 128;
            int hh = idx >> 7, si = idx & 127;
            at[hh][si] = g_sc[(size_t)(b * Hh + hh) * Ss + sbase + sc + si];
        }
        __syncthreads();
        const float* hp = g_hs + (size_t)(b * Ss + sbase + sc) * Ee + e;
        #pragma unroll 4
        for (int si = 0; si < 128; si++) {
            float x = hp[(size_t)si * Ee];
            #pragma unroll
            for (int hh = 0; hh < 16; hh++) acc[hh] += at[hh][si] * x;
        }
        __syncthreads();
    }
    #pragma unroll
    for (int hh = 0; hh < 16; hh++)
        atomicAdd(&g_c[(size_t)(b * Hh + hh) * Ee + e], acc[hh]);
}

// ---------------- out_attn = c @ v_w.T (per head) + v_b ----------------
__global__ __launch_bounds__(256) void vproj_kernel(const float* __restrict__ vw,
                                                    const float* __restrict__ vb) {
    int b = blockIdx.y;
    int warp = threadIdx.x >> 5, lane = threadIdx.x & 31;
    int j = blockIdx.x * 8 + warp;
    int hh = j >> 7;
    const float4* crow = reinterpret_cast<const float4*>(g_c + (size_t)(b * Hh + hh) * Ee);
    const float4* wrow = reinterpret_cast<const float4*>(vw + (size_t)j * Ee);
    float acc = 0.f;
    #pragma unroll
    for (int it = 0; it < 16; it++) {
        int i4 = it * 32 + lane;
        float4 a = crow[i4], w = wrow[i4];
        acc += a.x * w.x + a.y * w.y + a.z * w.z + a.w * w.w;
    }
    #pragma unroll
    for (int o = 16; o; o >>= 1) acc += __shfl_xor_sync(0xffffffffu, acc, o);
    if (lane == 0) g_oattn[b * Ee + j] = acc + vb[j];
}

// ---------------- out = out_attn @ out_w.T + out_b ----------------
__global__ __launch_bounds__(256) void oproj_kernel(const float* __restrict__ ow,
                                                    const float* __restrict__ ob,
                                                    float* __restrict__ out) {
    int b = blockIdx.y;
    int warp = threadIdx.x >> 5, lane = threadIdx.x & 31;
    int j = blockIdx.x * 8 + warp;
    const float4* arow = reinterpret_cast<const float4*>(g_oattn + (size_t)b * Ee);
    const float4* wrow = reinterpret_cast<const float4*>(ow + (size_t)j * Ee);
    float acc = 0.f;
    #pragma unroll
    for (int it = 0; it < 16; it++) {
        int i4 = it * 32 + lane;
        float4 a = arow[i4], w = wrow[i4];
        acc += a.x * w.x + a.y * w.y + a.z * w.z + a.w * w.w;
    }
    #pragma unroll
    for (int o = 16; o; o >>= 1) acc += __shfl_xor_sync(0xffffffffu, acc, o);
    if (lane == 0) out[b * Ee + j] = acc + ob[j];
}

// ---------------- launch ----------------
extern "C" void kernel_launch(void* const* d_in, const int* in_sizes, int n_in,
                              void* d_out, int out_size) {
    const float* hs_in = (const float*)d_in[0];
    const int*   ids   = (const int*)d_in[1];
    const float* lnw = (const float*)d_in[2];
    const float* lnb = (const float*)d_in[3];
    const float* qw  = (const float*)d_in[4];
    const float* qb  = (const float*)d_in[5];
    const float* kw  = (const float*)d_in[6];
    const float* kb  = (const float*)d_in[7];
    const float* vw  = (const float*)d_in[8];
    const float* vb  = (const float*)d_in[9];
    const float* ow  = (const float*)d_in[10];
    const float* ob  = (const float*)d_in[11];
    float* out = (float*)d_out;

    ln_kernel<<<Bb * Ss, 256>>>(hs_in, lnw, lnb);
    ix_kernel<<<Bb, 256>>>(ids);
    q_kernel<<<dim3(Ee / 8, Bb), 256>>>(qw, qb);
    scores_kernel<<<dim3(Ss / 128, Hh, Bb), 256>>>(kw, kb);
    softmax_kernel<<<Bb * Hh, 256>>>();
    zero_c_kernel<<<(Bb * Hh * Ee + 255) / 256, 256>>>();
    cvec_kernel<<<dim3(Ee / 128, Bb, 8), 128>>>();
    vproj_kernel<<<dim3(Ee / 8, Bb), 256>>>(vw, vb);
    oproj_kernel<<<dim3(Ee / 8, Bb), 256>>>(ow, ob, out);
}

// round 4
// speedup vs baseline: 1.4775x; 1.4775x over previous
#include <cuda_runtime.h>
#include <cuda_fp16.h>
#include <cstdint>
#include <math.h>

#define Bb 8
#define Ss 2048
#define Ee 2048
#define Hh 16
#define Dd 128
#define PADTOK 50257

// ---------------- scratch (device globals: allocation-free) ----------------
__device__ __half g_hsH[(size_t)Bb * Ss * Ee];   // hi fp16 split of LN output (32MB)
__device__ __half g_hsL[(size_t)Bb * Ss * Ee];   // lo fp16 split (32MB)
__device__ __half g_kwF[(size_t)Ee * Ee];        // k_w in fp16 (8MB)
__device__ float g_q[Bb * Ee];
__device__ float g_sc[Bb * Hh * Ss];
__device__ float g_c[Bb * Hh * Ee];
__device__ float g_oattn[Bb * Ee];
__device__ int   g_ix[Bb];

// ---------------- helpers ----------------
__device__ __forceinline__ void splitp_h(float f0, float f1, uint32_t& hi, uint32_t& lo) {
    __half2 Hv = __floats2half2_rn(f0, f1);
    float r0 = f0 - __low2float(Hv);
    float r1 = f1 - __high2float(Hv);
    __half2 Lv = __floats2half2_rn(r0, r1);
    hi = *reinterpret_cast<uint32_t*>(&Hv);
    lo = *reinterpret_cast<uint32_t*>(&Lv);
}

__device__ __forceinline__ float h2sum(uint32_t h, uint32_t l, int sel) {
    __half2 hv = *reinterpret_cast<__half2*>(&h);
    __half2 lv = *reinterpret_cast<__half2*>(&l);
    return sel ? (__high2float(hv) + __high2float(lv))
               : (__low2float(hv) + __low2float(lv));
}

// ---------------- LayerNorm + fp16 hi/lo split ----------------
__global__ __launch_bounds__(256) void ln_kernel(const float* __restrict__ x,
                                                 const float* __restrict__ w,
                                                 const float* __restrict__ bias) {
    int row = blockIdx.x;
    const float4* xin = reinterpret_cast<const float4*>(x + (size_t)row * Ee);
    int tid = threadIdx.x;
    float4 v0 = xin[tid];
    float4 v1 = xin[tid + 256];
    float s  = v0.x + v0.y + v0.z + v0.w + v1.x + v1.y + v1.z + v1.w;
    float s2 = v0.x*v0.x + v0.y*v0.y + v0.z*v0.z + v0.w*v0.w
             + v1.x*v1.x + v1.y*v1.y + v1.z*v1.z + v1.w*v1.w;
    #pragma unroll
    for (int o = 16; o; o >>= 1) {
        s  += __shfl_xor_sync(0xffffffffu, s, o);
        s2 += __shfl_xor_sync(0xffffffffu, s2, o);
    }
    __shared__ float red[16];
    __shared__ float mv[2];
    int warp = tid >> 5, lane = tid & 31;
    if (lane == 0) { red[warp] = s; red[warp + 8] = s2; }
    __syncthreads();
    if (tid == 0) {
        float a = 0.f, b2 = 0.f;
        #pragma unroll
        for (int i = 0; i < 8; i++) { a += red[i]; b2 += red[i + 8]; }
        float mu  = a / (float)Ee;
        float var = b2 / (float)Ee - mu * mu;
        mv[0] = mu; mv[1] = rsqrtf(var + 1e-5f);
    }
    __syncthreads();
    float mu = mv[0], rs = mv[1];
    const float4* wv4 = reinterpret_cast<const float4*>(w);
    const float4* bv4 = reinterpret_cast<const float4*>(bias);
    uint2* outH = reinterpret_cast<uint2*>(g_hsH + (size_t)row * Ee);
    uint2* outL = reinterpret_cast<uint2*>(g_hsL + (size_t)row * Ee);
    {
        float4 wv = wv4[tid], bv = bv4[tid], o;
        o.x = (v0.x - mu) * rs * wv.x + bv.x;
        o.y = (v0.y - mu) * rs * wv.y + bv.y;
        o.z = (v0.z - mu) * rs * wv.z + bv.z;
        o.w = (v0.w - mu) * rs * wv.w + bv.w;
        uint32_t h0, l0, h1, l1;
        splitp_h(o.x, o.y, h0, l0); splitp_h(o.z, o.w, h1, l1);
        outH[tid] = make_uint2(h0, h1);
        outL[tid] = make_uint2(l0, l1);
    }
    {
        float4 wv = wv4[tid + 256], bv = bv4[tid + 256], o;
        o.x = (v1.x - mu) * rs * wv.x + bv.x;
        o.y = (v1.y - mu) * rs * wv.y + bv.y;
        o.z = (v1.z - mu) * rs * wv.z + bv.z;
        o.w = (v1.w - mu) * rs * wv.w + bv.w;
        uint32_t h0, l0, h1, l1;
        splitp_h(o.x, o.y, h0, l0); splitp_h(o.z, o.w, h1, l1);
        outH[tid + 256] = make_uint2(h0, h1);
        outL[tid + 256] = make_uint2(l0, l1);
    }
}

// ---------------- k_w fp16 convert ----------------
__global__ __launch_bounds__(256) void kwconv_kernel(const float* __restrict__ kw) {
    size_t i4 = (size_t)blockIdx.x * 256 + threadIdx.x;      // one float4 each
    float4 v = reinterpret_cast<const float4*>(kw)[i4];
    __half2 a = __floats2half2_rn(v.x, v.y);
    __half2 b = __floats2half2_rn(v.z, v.w);
    reinterpret_cast<uint2*>(g_kwF)[i4] =
        make_uint2(*reinterpret_cast<uint32_t*>(&a), *reinterpret_cast<uint32_t*>(&b));
}

// ---------------- last non-pad index ----------------
__global__ __launch_bounds__(256) void ix_kernel(const int* __restrict__ ids) {
    int b = blockIdx.x;
    int m = -1;
    for (int s = threadIdx.x; s < Ss; s += 256)
        if (ids[b * Ss + s] != PADTOK) m = s;
    #pragma unroll
    for (int o = 16; o; o >>= 1) m = max(m, __shfl_xor_sync(0xffffffffu, m, o));
    __shared__ int rm[8];
    int warp = threadIdx.x >> 5, lane = threadIdx.x & 31;
    if (lane == 0) rm[warp] = m;
    __syncthreads();
    if (threadIdx.x == 0) {
        int mm = -1;
        #pragma unroll
        for (int i = 0; i < 8; i++) mm = max(mm, rm[i]);
        g_ix[b] = (mm < 0) ? 0 : mm;
    }
}

// ---------------- q = h_last @ q_w.T + q_b ----------------
__global__ __launch_bounds__(256) void q_kernel(const float* __restrict__ qw,
                                                const float* __restrict__ qb) {
    int b = blockIdx.y;
    int warp = threadIdx.x >> 5, lane = threadIdx.x & 31;
    int j = blockIdx.x * 8 + warp;
    size_t hb = ((size_t)(b * Ss) + g_ix[b]) * Ee;
    const uint2* hH = reinterpret_cast<const uint2*>(g_hsH + hb);
    const uint2* hL = reinterpret_cast<const uint2*>(g_hsL + hb);
    const float4* wrow = reinterpret_cast<const float4*>(qw + (size_t)j * Ee);
    float acc = 0.f;
    #pragma unroll
    for (int it = 0; it < 16; it++) {
        int i4 = it * 32 + lane;
        uint2 hv = hH[i4], lv = hL[i4];
        float4 w = wrow[i4];
        acc += h2sum(hv.x, lv.x, 0) * w.x;
        acc += h2sum(hv.x, lv.x, 1) * w.y;
        acc += h2sum(hv.y, lv.y, 0) * w.z;
        acc += h2sum(hv.y, lv.y, 1) * w.w;
    }
    #pragma unroll
    for (int o = 16; o; o >>= 1) acc += __shfl_xor_sync(0xffffffffu, acc, o);
    if (lane == 0) g_q[b * Ee + j] = acc + qb[j];
}

// ---------------- scores: K GEMM (fp16 2xMMA: A split hi/lo, B single) ------------
// per CTA: 128 s-rows x 128 d-cols (one head), K=2048 in chunks of 32,
// cp.async double-buffered smem, scalar LDS fragment feeds (pad-20 layout).

__device__ __forceinline__ void mma_f16(float c[4], uint32_t a0, uint32_t a1, uint32_t a2,
                                        uint32_t a3, uint32_t b0, uint32_t b1) {
    asm volatile(
        "mma.sync.aligned.m16n8k16.row.col.f32.f16.f16.f32 "
        "{%0,%1,%2,%3}, {%4,%5,%6,%7}, {%8,%9}, {%0,%1,%2,%3};"
        : "+f"(c[0]), "+f"(c[1]), "+f"(c[2]), "+f"(c[3])
        : "r"(a0), "r"(a1), "r"(a2), "r"(a3), "r"(b0), "r"(b1));
}

__device__ __forceinline__ void cp16(uint32_t dst, const void* src) {
    asm volatile("cp.async.cg.shared.global [%0], [%1], 16;" :: "r"(dst), "l"(src) : "memory");
}
#define CP_COMMIT() asm volatile("cp.async.commit_group;" ::: "memory")
#define CP_WAIT1()  asm volatile("cp.async.wait_group 1;" ::: "memory")
#define CP_WAIT0()  asm volatile("cp.async.wait_group 0;" ::: "memory")

// word-offsets inside one stage (uint32 units): row stride 20 (80B, 16B-aligned pad)
#define AH_OFF 0
#define AL_OFF 2560
#define BB_OFF 5120
#define STAGE_W 7680                       // words per stage (30720 B)
#define DYN_SMEM (2 * STAGE_W * 4)         // 61440 B

__global__ void __launch_bounds__(256, 2) scores_kernel(const float* __restrict__ kb) {
    extern __shared__ uint32_t smw[];
    __shared__ float qs[128], kbs[128];
    __shared__ double finv[32];
    __shared__ float red[128][2];

    const int tid = threadIdx.x;
    const int b = blockIdx.z, h = blockIdx.y, s0 = blockIdx.x * 128;
    if (tid < 128) { qs[tid] = g_q[b * Ee + h * Dd + tid]; kbs[tid] = kb[h * Dd + tid]; }
    if (tid < 32) finv[tid] = exp(-((double)(2 * tid) / 64.0) * 9.210340371976184);

    uint32_t sb;
    asm("{ .reg .u64 t; cvta.to.shared.u64 t, %1; cvt.u32.u64 %0, t; }" : "=r"(sb) : "l"(smw));

    const int warp = tid >> 5, lane = tid & 31;
    const int wm = warp >> 1, wn = warp & 1;
    const int g = lane >> 2, tq = lane & 3;

    float acc[2][8][4];
    #pragma unroll
    for (int i = 0; i < 2; i++)
        #pragma unroll
        for (int j = 0; j < 8; j++)
            #pragma unroll
            for (int k = 0; k < 4; k++) acc[i][j][k] = 0.f;

    // load addressing: per array, 512 cp16 (128 rows x 4); this thread does ids {tid, tid+256}
    const char* aHb = (const char*)(g_hsH + (size_t)(b * Ss + s0) * Ee);
    const char* aLb = (const char*)(g_hsL + (size_t)(b * Ss + s0) * Ee);
    const char* bFb = (const char*)(g_kwF + (size_t)(h * Dd) * Ee);

#define LOAD_STAGE(st, k0)                                                      \
    {                                                                           \
        uint32_t sbase = sb + (st) * (STAGE_W * 4);                             \
        _Pragma("unroll")                                                       \
        for (int i = 0; i < 2; i++) {                                           \
            int id = tid + i * 256;                                             \
            int row = id >> 2, q = id & 3;                                      \
            uint32_t doff = (uint32_t)(row * 80 + q * 16);                      \
            size_t goff = (size_t)row * 4096 + (size_t)(k0) * 2 + q * 16;       \
            cp16(sbase + AH_OFF * 4 + doff, aHb + goff);                        \
            cp16(sbase + AL_OFF * 4 + doff, aLb + goff);                        \
            cp16(sbase + BB_OFF * 4 + doff, bFb + goff);                        \
        }                                                                       \
        CP_COMMIT();                                                            \
    }

    LOAD_STAGE(0, 0);

    for (int k = 0; k < 64; k++) {
        const int s = k & 1;
        if (k + 1 < 64) { LOAD_STAGE(s ^ 1, (k + 1) * 32); CP_WAIT1(); }
        else           { CP_WAIT0(); }
        __syncthreads();

        const uint32_t* AH = smw + s * STAGE_W + AH_OFF;
        const uint32_t* AL = smw + s * STAGE_W + AL_OFF;
        const uint32_t* BF = smw + s * STAGE_W + BB_OFF;

        #pragma unroll
        for (int kk2 = 0; kk2 < 16; kk2 += 8) {
            uint32_t aH[2][4], aL[2][4];
            #pragma unroll
            for (int mt = 0; mt < 2; mt++) {
                int r = wm * 32 + mt * 16 + g;
                aH[mt][0] = AH[r * 20 + kk2 + tq];            aH[mt][1] = AH[(r + 8) * 20 + kk2 + tq];
                aH[mt][2] = AH[r * 20 + kk2 + 4 + tq];        aH[mt][3] = AH[(r + 8) * 20 + kk2 + 4 + tq];
                aL[mt][0] = AL[r * 20 + kk2 + tq];            aL[mt][1] = AL[(r + 8) * 20 + kk2 + tq];
                aL[mt][2] = AL[r * 20 + kk2 + 4 + tq];        aL[mt][3] = AL[(r + 8) * 20 + kk2 + 4 + tq];
            }
            #pragma unroll
            for (int nt = 0; nt < 8; nt++) {
                int n = wn * 64 + nt * 8 + g;
                uint32_t b0 = BF[n * 20 + kk2 + tq];
                uint32_t b1 = BF[n * 20 + kk2 + 4 + tq];
                #pragma unroll
                for (int mt = 0; mt < 2; mt++) {
                    mma_f16(acc[mt][nt], aH[mt][0], aH[mt][1], aH[mt][2], aH[mt][3], b0, b1);
                    mma_f16(acc[mt][nt], aL[mt][0], aL[mt][1], aL[mt][2], aL[mt][3], b0, b1);
                }
            }
        }
        __syncthreads();
    }

    // epilogue: k += k_b, fold RoPE(pos=s) onto q, dot, reduce
    const double INV2PI = 0.15915494309189535;
    const double TWOPI  = 6.283185307179586;
    #pragma unroll
    for (int mt = 0; mt < 2; mt++) {
        #pragma unroll
        for (int half = 0; half < 2; half++) {
            int rl = wm * 32 + mt * 16 + half * 8 + g;
            int s = s0 + rl;
            float partial = 0.f;
            #pragma unroll
            for (int nt = 0; nt < 8; nt++) {
                int col = wn * 64 + nt * 8 + tq * 2;
                float k0v = acc[mt][nt][half * 2 + 0] + kbs[col];
                float k1v = acc[mt][nt][half * 2 + 1] + kbs[col + 1];
                if (col < 64) {                         // uniform per warp (wn==0)
                    int j = col >> 1;
                    double ang = (double)s * finv[j];
                    double kq = rint(ang * INV2PI);
                    float r = (float)(ang - kq * TWOPI);
                    float sn, cs;
                    __sincosf(r, &sn, &cs);
                    float qe0 = qs[col] * cs + qs[col + 1] * sn;
                    float qe1 = qs[col + 1] * cs - qs[col] * sn;
                    partial += k0v * qe0 + k1v * qe1;
                } else {
                    partial += k0v * qs[col] + k1v * qs[col + 1];
                }
            }
            partial += __shfl_xor_sync(0xffffffffu, partial, 1);
            partial += __shfl_xor_sync(0xffffffffu, partial, 2);
            if (tq == 0) red[rl][wn] = partial;
        }
    }
    __syncthreads();
    if (tid < 128)
        g_sc[(size_t)(b * Hh + h) * Ss + s0 + tid] = red[tid][0] + red[tid][1];
}

// ---------------- softmax over s (per b,h) ----------------
__global__ __launch_bounds__(256) void softmax_kernel() {
    int row = blockIdx.x;
    float* pp = g_sc + (size_t)row * Ss;
    int tid = threadIdx.x;
    float v[8];
    float m = -1e30f;
    #pragma unroll
    for (int i = 0; i < 8; i++) { v[i] = pp[tid + i * 256]; m = fmaxf(m, v[i]); }
    #pragma unroll
    for (int o = 16; o; o >>= 1) m = fmaxf(m, __shfl_xor_sync(0xffffffffu, m, o));
    __shared__ float rs[8];
    int warp = tid >> 5, lane = tid & 31;
    if (lane == 0) rs[warp] = m;
    __syncthreads();
    float mm = rs[0];
    #pragma unroll
    for (int i = 1; i < 8; i++) mm = fmaxf(mm, rs[i]);
    float ssum = 0.f;
    #pragma unroll
    for (int i = 0; i < 8; i++) { v[i] = expf(v[i] - mm); ssum += v[i]; }
    #pragma unroll
    for (int o = 16; o; o >>= 1) ssum += __shfl_xor_sync(0xffffffffu, ssum, o);
    __syncthreads();
    if (lane == 0) rs[warp] = ssum;
    __syncthreads();
    float tot = 0.f;
    #pragma unroll
    for (int i = 0; i < 8; i++) tot += rs[i];
    float inv = 1.f / tot;
    #pragma unroll
    for (int i = 0; i < 8; i++) pp[tid + i * 256] = v[i] * inv;
}

// ---------------- c[b,h,e] = sum_s attn * hs ----------------
__global__ void zero_c_kernel() {
    int i = blockIdx.x * blockDim.x + threadIdx.x;
    if (i < Bb * Hh * Ee) g_c[i] = 0.f;
}

__global__ __launch_bounds__(128) void cvec_kernel() {
    __shared__ float at[16][128];
    int tid = threadIdx.x;
    int b = blockIdx.y;
    int e = blockIdx.x * 128 + tid;
    int sbase = blockIdx.z * 256;
    float acc[16];
    #pragma unroll
    for (int i = 0; i < 16; i++) acc[i] = 0.f;
    for (int sc = 0; sc < 256; sc += 128) {
        #pragma unroll
        for (int i = 0; i < 16; i++) {
            int idx = tid + i * 128;
            int hh = idx >> 7, si = idx & 127;
            at[hh][si] = g_sc[(size_t)(b * Hh + hh) * Ss + sbase + sc + si];
        }
        __syncthreads();
        size_t base = (size_t)(b * Ss + sbase + sc) * Ee + e;
        #pragma unroll 4
        for (int si = 0; si < 128; si++) {
            float x = __half2float(g_hsH[base + (size_t)si * Ee])
                    + __half2float(g_hsL[base + (size_t)si * Ee]);
            #pragma unroll
            for (int hh = 0; hh < 16; hh++) acc[hh] += at[hh][si] * x;
        }
        __syncthreads();
    }
    #pragma unroll
    for (int hh = 0; hh < 16; hh++)
        atomicAdd(&g_c[(size_t)(b * Hh + hh) * Ee + e], acc[hh]);
}

// ---------------- out_attn = c @ v_w.T (per head) + v_b ----------------
__global__ __launch_bounds__(256) void vproj_kernel(const float* __restrict__ vw,
                                                    const float* __restrict__ vb) {
    int b = blockIdx.y;
    int warp = threadIdx.x >> 5, lane = threadIdx.x & 31;
    int j = blockIdx.x * 8 + warp;
    int hh = j >> 7;
    const float4* crow = reinterpret_cast<const float4*>(g_c + (size_t)(b * Hh + hh) * Ee);
    const float4* wrow = reinterpret_cast<const float4*>(vw + (size_t)j * Ee);
    float acc = 0.f;
    #pragma unroll
    for (int it = 0; it < 16; it++) {
        int i4 = it * 32 + lane;
        float4 a = crow[i4], w = wrow[i4];
        acc += a.x * w.x + a.y * w.y + a.z * w.z + a.w * w.w;
    }
    #pragma unroll
    for (int o = 16; o; o >>= 1) acc += __shfl_xor_sync(0xffffffffu, acc, o);
    if (lane == 0) g_oattn[b * Ee + j] = acc + vb[j];
}

// ---------------- out = out_attn @ out_w.T + out_b ----------------
__global__ __launch_bounds__(256) void oproj_kernel(const float* __restrict__ ow,
                                                    const float* __restrict__ ob,
                                                    float* __restrict__ out) {
    int b = blockIdx.y;
    int warp = threadIdx.x >> 5, lane = threadIdx.x & 31;
    int j = blockIdx.x * 8 + warp;
    const float4* arow = reinterpret_cast<const float4*>(g_oattn + (size_t)b * Ee);
    const float4* wrow = reinterpret_cast<const float4*>(ow + (size_t)j * Ee);
    float acc = 0.f;
    #pragma unroll
    for (int it = 0; it < 16; it++) {
        int i4 = it * 32 + lane;
        float4 a = arow[i4], w = wrow[i4];
        acc += a.x * w.x + a.y * w.y + a.z * w.z + a.w * w.w;
    }
    #pragma unroll
    for (int o = 16; o; o >>= 1) acc += __shfl_xor_sync(0xffffffffu, acc, o);
    if (lane == 0) out[b * Ee + j] = acc + ob[j];
}

// ---------------- launch ----------------
extern "C" void kernel_launch(void* const* d_in, const int* in_sizes, int n_in,
                              void* d_out, int out_size) {
    const float* hs_in = (const float*)d_in[0];
    const int*   ids   = (const int*)d_in[1];
    const float* lnw = (const float*)d_in[2];
    const float* lnb = (const float*)d_in[3];
    const float* qw  = (const float*)d_in[4];
    const float* qb  = (const float*)d_in[5];
    const float* kw  = (const float*)d_in[6];
    const float* kb  = (const float*)d_in[7];
    const float* vw  = (const float*)d_in[8];
    const float* vb  = (const float*)d_in[9];
    const float* ow  = (const float*)d_in[10];
    const float* ob  = (const float*)d_in[11];
    float* out = (float*)d_out;

    cudaFuncSetAttribute(scores_kernel, cudaFuncAttributeMaxDynamicSharedMemorySize, DYN_SMEM);

    ln_kernel<<<Bb * Ss, 256>>>(hs_in, lnw, lnb);
    kwconv_kernel<<<(Ee * Ee / 4) / 256, 256>>>(kw);
    ix_kernel<<<Bb, 256>>>(ids);
    q_kernel<<<dim3(Ee / 8, Bb), 256>>>(qw, qb);
    scores_kernel<<<dim3(Ss / 128, Hh, Bb), 256, DYN_SMEM>>>(kb);
    softmax_kernel<<<Bb * Hh, 256>>>();
    zero_c_kernel<<<(Bb * Hh * Ee + 255) / 256, 256>>>();
    cvec_kernel<<<dim3(Ee / 128, Bb, 8), 128>>>();
    vproj_kernel<<<dim3(Ee / 8, Bb), 256>>>(vw, vb);
    oproj_kernel<<<dim3(Ee / 8, Bb), 256>>>(ow, ob, out);
}

// round 5
// speedup vs baseline: 1.7350x; 1.1743x over previous
#include <cuda_runtime.h>
#include <cuda_fp16.h>
#include <cstdint>
#include <math.h>

#define Bb 8
#define Ss 2048
#define Ee 2048
#define Hh 16
#define Dd 128
#define PADTOK 50257

// ---------------- scratch (device globals: allocation-free) ----------------
__device__ __half g_hsH[(size_t)Bb * Ss * Ee];   // hi fp16 split of LN output
__device__ __half g_hsL[(size_t)Bb * Ss * Ee];   // lo fp16 split
__device__ __half g_pH[(size_t)Bb * Hh * 72 * Ee];  // projected weights hi
__device__ __half g_pL[(size_t)Bb * Hh * 72 * Ee];  // projected weights lo
__device__ float g_q[Bb * Ee];
__device__ float g_sc[Bb * Hh * Ss];
__device__ float g_c[Bb * Hh * Ee];
__device__ float g_oattn[Bb * Ee];
__device__ int   g_ix[Bb];

// ---------------- helpers ----------------
__device__ __forceinline__ void splitp_h(float f0, float f1, uint32_t& hi, uint32_t& lo) {
    __half2 Hv = __floats2half2_rn(f0, f1);
    float r0 = f0 - __low2float(Hv);
    float r1 = f1 - __high2float(Hv);
    __half2 Lv = __floats2half2_rn(r0, r1);
    hi = *reinterpret_cast<uint32_t*>(&Hv);
    lo = *reinterpret_cast<uint32_t*>(&Lv);
}

__device__ __forceinline__ float h2sum(uint32_t h, uint32_t l, int sel) {
    __half2 hv = *reinterpret_cast<__half2*>(&h);
    __half2 lv = *reinterpret_cast<__half2*>(&l);
    return sel ? (__high2float(hv) + __high2float(lv))
               : (__low2float(hv) + __low2float(lv));
}

// ---------------- LayerNorm + fp16 hi/lo split ----------------
__global__ __launch_bounds__(256) void ln_kernel(const float* __restrict__ x,
                                                 const float* __restrict__ w,
                                                 const float* __restrict__ bias) {
    int row = blockIdx.x;
    const float4* xin = reinterpret_cast<const float4*>(x + (size_t)row * Ee);
    int tid = threadIdx.x;
    float4 v0 = xin[tid];
    float4 v1 = xin[tid + 256];
    float s  = v0.x + v0.y + v0.z + v0.w + v1.x + v1.y + v1.z + v1.w;
    float s2 = v0.x*v0.x + v0.y*v0.y + v0.z*v0.z + v0.w*v0.w
             + v1.x*v1.x + v1.y*v1.y + v1.z*v1.z + v1.w*v1.w;
    #pragma unroll
    for (int o = 16; o; o >>= 1) {
        s  += __shfl_xor_sync(0xffffffffu, s, o);
        s2 += __shfl_xor_sync(0xffffffffu, s2, o);
    }
    __shared__ float red[16];
    __shared__ float mv[2];
    int warp = tid >> 5, lane = tid & 31;
    if (lane == 0) { red[warp] = s; red[warp + 8] = s2; }
    __syncthreads();
    if (tid == 0) {
        float a = 0.f, b2 = 0.f;
        #pragma unroll
        for (int i = 0; i < 8; i++) { a += red[i]; b2 += red[i + 8]; }
        float mu  = a / (float)Ee;
        float var = b2 / (float)Ee - mu * mu;
        mv[0] = mu; mv[1] = rsqrtf(var + 1e-5f);
    }
    __syncthreads();
    float mu = mv[0], rs = mv[1];
    const float4* wv4 = reinterpret_cast<const float4*>(w);
    const float4* bv4 = reinterpret_cast<const float4*>(bias);
    uint2* outH = reinterpret_cast<uint2*>(g_hsH + (size_t)row * Ee);
    uint2* outL = reinterpret_cast<uint2*>(g_hsL + (size_t)row * Ee);
    {
        float4 wv = wv4[tid], bv = bv4[tid], o;
        o.x = (v0.x - mu) * rs * wv.x + bv.x;
        o.y = (v0.y - mu) * rs * wv.y + bv.y;
        o.z = (v0.z - mu) * rs * wv.z + bv.z;
        o.w = (v0.w - mu) * rs * wv.w + bv.w;
        uint32_t h0, l0, h1, l1;
        splitp_h(o.x, o.y, h0, l0); splitp_h(o.z, o.w, h1, l1);
        outH[tid] = make_uint2(h0, h1);
        outL[tid] = make_uint2(l0, l1);
    }
    {
        float4 wv = wv4[tid + 256], bv = bv4[tid + 256], o;
        o.x = (v1.x - mu) * rs * wv.x + bv.x;
        o.y = (v1.y - mu) * rs * wv.y + bv.y;
        o.z = (v1.z - mu) * rs * wv.z + bv.z;
        o.w = (v1.w - mu) * rs * wv.w + bv.w;
        uint32_t h0, l0, h1, l1;
        splitp_h(o.x, o.y, h0, l0); splitp_h(o.z, o.w, h1, l1);
        outH[tid + 256] = make_uint2(h0, h1);
        outL[tid + 256] = make_uint2(l0, l1);
    }
}

// ---------------- last non-pad index ----------------
__global__ __launch_bounds__(256) void ix_kernel(const int* __restrict__ ids) {
    int b = blockIdx.x;
    int m = -1;
    for (int s = threadIdx.x; s < Ss; s += 256)
        if (ids[b * Ss + s] != PADTOK) m = s;
    #pragma unroll
    for (int o = 16; o; o >>= 1) m = max(m, __shfl_xor_sync(0xffffffffu, m, o));
    __shared__ int rm[8];
    int warp = threadIdx.x >> 5, lane = threadIdx.x & 31;
    if (lane == 0) rm[warp] = m;
    __syncthreads();
    if (threadIdx.x == 0) {
        int mm = -1;
        #pragma unroll
        for (int i = 0; i < 8; i++) mm = max(mm, rm[i]);
        g_ix[b] = (mm < 0) ? 0 : mm;
    }
}

// ---------------- q = h_last @ q_w.T + q_b ----------------
__global__ __launch_bounds__(256) void q_kernel(const float* __restrict__ qw,
                                                const float* __restrict__ qb) {
    int b = blockIdx.y;
    int warp = threadIdx.x >> 5, lane = threadIdx.x & 31;
    int j = blockIdx.x * 8 + warp;
    size_t hb = ((size_t)(b * Ss) + g_ix[b]) * Ee;
    const uint2* hH = reinterpret_cast<const uint2*>(g_hsH + hb);
    const uint2* hL = reinterpret_cast<const uint2*>(g_hsL + hb);
    const float4* wrow = reinterpret_cast<const float4*>(qw + (size_t)j * Ee);
    float acc = 0.f;
    #pragma unroll
    for (int it = 0; it < 16; it++) {
        int i4 = it * 32 + lane;
        uint2 hv = hH[i4], lv = hL[i4];
        float4 w = wrow[i4];
        acc += h2sum(hv.x, lv.x, 0) * w.x;
        acc += h2sum(hv.x, lv.x, 1) * w.y;
        acc += h2sum(hv.y, lv.y, 0) * w.z;
        acc += h2sum(hv.y, lv.y, 1) * w.w;
    }
    #pragma unroll
    for (int o = 16; o; o >>= 1) acc += __shfl_xor_sync(0xffffffffu, acc, o);
    if (lane == 0) g_q[b * Ee + j] = acc + qb[j];
}

// ---------------- P matrices: fold q into k_w (RoPE projection) ----------------
// P[bh][n][e], n<32: cos-coeff A_j; 32<=n<64: sin-coeff B_j; n=64: C; 65..71: 0
__global__ __launch_bounds__(256) void pmat_kernel(const float* __restrict__ kw) {
    int tid = threadIdx.x;
    int e = blockIdx.x * 256 + tid;
    int h = blockIdx.y, b = blockIdx.z;
    __shared__ float qs[128];
    if (tid < 128) qs[tid] = g_q[b * Ee + h * Dd + tid];
    __syncthreads();
    size_t pbase = ((size_t)(b * Hh + h)) * 72 * Ee + e;
    const float* kwb = kw + (size_t)h * Dd * Ee + e;
    #pragma unroll 4
    for (int j = 0; j < 32; j++) {
        float k0 = kwb[(size_t)(2 * j) * Ee];
        float k1 = kwb[(size_t)(2 * j + 1) * Ee];
        float A  = k0 * qs[2 * j]     + k1 * qs[2 * j + 1];
        float Bv = k0 * qs[2 * j + 1] - k1 * qs[2 * j];
        __half ah = __float2half_rn(A);
        __half al = __float2half_rn(A - __half2float(ah));
        __half bh = __float2half_rn(Bv);
        __half bl = __float2half_rn(Bv - __half2float(bh));
        g_pH[pbase + (size_t)j * Ee] = ah;
        g_pL[pbase + (size_t)j * Ee] = al;
        g_pH[pbase + (size_t)(32 + j) * Ee] = bh;
        g_pL[pbase + (size_t)(32 + j) * Ee] = bl;
    }
    float C = 0.f;
    #pragma unroll 8
    for (int d = 64; d < 128; d++) C += kwb[(size_t)d * Ee] * qs[d];
    __half ch = __float2half_rn(C);
    __half cl = __float2half_rn(C - __half2float(ch));
    g_pH[pbase + (size_t)64 * Ee] = ch;
    g_pL[pbase + (size_t)64 * Ee] = cl;
    #pragma unroll
    for (int n = 65; n < 72; n++) {
        g_pH[pbase + (size_t)n * Ee] = __float2half_rn(0.f);
        g_pL[pbase + (size_t)n * Ee] = __float2half_rn(0.f);
    }
}

// ---------------- GEMM G = hs @ P^T (3-term fp16 split) + fused combine ----------
__device__ __forceinline__ void mma_f16(float c[4], uint32_t a0, uint32_t a1, uint32_t a2,
                                        uint32_t a3, uint32_t b0, uint32_t b1) {
    asm volatile(
        "mma.sync.aligned.m16n8k16.row.col.f32.f16.f16.f32 "
        "{%0,%1,%2,%3}, {%4,%5,%6,%7}, {%8,%9}, {%0,%1,%2,%3};"
        : "+f"(c[0]), "+f"(c[1]), "+f"(c[2]), "+f"(c[3])
        : "r"(a0), "r"(a1), "r"(a2), "r"(a3), "r"(b0), "r"(b1));
}

__device__ __forceinline__ void ldsm4(uint32_t r[4], uint32_t a) {
    asm volatile("ldmatrix.sync.aligned.m8n8.x4.shared.b16 {%0,%1,%2,%3}, [%4];"
                 : "=r"(r[0]), "=r"(r[1]), "=r"(r[2]), "=r"(r[3]) : "r"(a));
}
__device__ __forceinline__ void ldsm2(uint32_t r[2], uint32_t a) {
    asm volatile("ldmatrix.sync.aligned.m8n8.x2.shared.b16 {%0,%1}, [%2];"
                 : "=r"(r[0]), "=r"(r[1]) : "r"(a));
}

__device__ __forceinline__ void cp16(uint32_t dst, const void* src) {
    asm volatile("cp.async.cg.shared.global [%0], [%1], 16;" :: "r"(dst), "l"(src) : "memory");
}
#define CP_COMMIT() asm volatile("cp.async.commit_group;" ::: "memory")
#define CP_WAIT1()  asm volatile("cp.async.wait_group 1;" ::: "memory")
#define CP_WAIT0()  asm volatile("cp.async.wait_group 0;" ::: "memory")

// stage layout (byte offsets): A tiles 128rows x 128B (K64 fp16), B tiles 72rows x 128B
#define GA_H 0
#define GA_L 16384
#define GB_H 32768
#define GB_L 41984
#define GM_STAGE 51200
#define GEMM_SMEM (2 * GM_STAGE)

template<int NT>
__device__ __forceinline__ void mma_chunk(uint32_t base, int nbase, int rA, int lane,
                                          float acc[2][5][4]) {
    #pragma unroll
    for (int kk = 0; kk < 4; kk++) {
        const int kkc = kk * 2;
        uint32_t aH[2][4], aL[2][4];
        #pragma unroll
        for (int mt = 0; mt < 2; mt++) {
            int row = rA + mt * 16 + (lane & 15);
            int c16 = kkc + (lane >> 4);
            uint32_t off = (uint32_t)(row * 128 + ((c16 ^ (row & 7)) << 4));
            ldsm4(aH[mt], base + GA_H + off);
            ldsm4(aL[mt], base + GA_L + off);
        }
        uint32_t bH[10], bL[10];
        #pragma unroll
        for (int tp = 0; tp < NT / 2; tp++) {
            int row = nbase + tp * 16 + ((lane >> 4) << 3) + (lane & 7);
            int c16 = kkc + ((lane >> 3) & 1);
            uint32_t off = (uint32_t)(row * 128 + ((c16 ^ (row & 7)) << 4));
            ldsm4(&bH[tp * 4], base + GB_H + off);
            ldsm4(&bL[tp * 4], base + GB_L + off);
        }
        if (NT & 1) {
            int row = nbase + (NT - 1) * 8 + (lane & 7);
            int c16 = kkc + (((lane & 15) >> 3) & 1);
            uint32_t off = (uint32_t)(row * 128 + ((c16 ^ (row & 7)) << 4));
            ldsm2(&bH[(NT - 1) * 2], base + GB_H + off);
            ldsm2(&bL[(NT - 1) * 2], base + GB_L + off);
        }
        #pragma unroll
        for (int nt = 0; nt < NT; nt++) {
            #pragma unroll
            for (int mt = 0; mt < 2; mt++) {
                mma_f16(acc[mt][nt], aH[mt][0], aH[mt][1], aH[mt][2], aH[mt][3],
                        bH[nt * 2], bH[nt * 2 + 1]);
                mma_f16(acc[mt][nt], aL[mt][0], aL[mt][1], aL[mt][2], aL[mt][3],
                        bH[nt * 2], bH[nt * 2 + 1]);
                mma_f16(acc[mt][nt], aH[mt][0], aH[mt][1], aH[mt][2], aH[mt][3],
                        bL[nt * 2], bL[nt * 2 + 1]);
            }
        }
    }
}

__global__ void __launch_bounds__(256, 2) gemm_scores(const float* __restrict__ kb) {
    extern __shared__ char dsm[];
    __shared__ float pbA[32], pbB[32], pbCs[1];
    __shared__ double finv[32];

    const int tid = threadIdx.x, warp = tid >> 5, lane = tid & 31;
    const int bh = blockIdx.y, b = bh >> 4, h = bh & 15;
    const int s0 = blockIdx.x * 128;

    if (tid < 32) {
        finv[tid] = exp(-((double)(2 * tid) / 64.0) * 9.210340371976184);
        float q0 = g_q[b * Ee + h * Dd + 2 * tid];
        float q1 = g_q[b * Ee + h * Dd + 2 * tid + 1];
        float k0 = kb[h * Dd + 2 * tid];
        float k1 = kb[h * Dd + 2 * tid + 1];
        pbA[tid] = q0 * k0 + q1 * k1;
        pbB[tid] = q1 * k0 - q0 * k1;
    } else if (tid == 32) {
        float a = 0.f;
        for (int d = 64; d < 128; d++) a += kb[h * Dd + d] * g_q[b * Ee + h * Dd + d];
        pbCs[0] = a;
    }

    uint32_t sb;
    asm("{ .reg .u64 t; cvta.to.shared.u64 t, %1; cvt.u32.u64 %0, t; }" : "=r"(sb) : "l"(dsm));

    const char* aHb = (const char*)(g_hsH + (size_t)(b * Ss + s0) * Ee);
    const char* aLb = (const char*)(g_hsL + (size_t)(b * Ss + s0) * Ee);
    const char* pHb = (const char*)(g_pH + (size_t)bh * 72 * Ee);
    const char* pLb = (const char*)(g_pL + (size_t)bh * 72 * Ee);

#define G_LOAD_STAGE(st, k0w)                                                     \
    {                                                                             \
        uint32_t sbase = sb + (st) * GM_STAGE;                                    \
        _Pragma("unroll")                                                         \
        for (int i = 0; i < 13; i++) {                                            \
            int id = tid + 256 * i;                                               \
            if (id < 3200) {                                                      \
                int arr = (id < 1024) ? 0 : (id < 2048) ? 1 : (id < 2624) ? 2 : 3;\
                int rid = id - ((arr == 0) ? 0 : (arr == 1) ? 1024                \
                                : (arr == 2) ? 2048 : 2624);                      \
                int row = rid >> 3, c = rid & 7;                                  \
                uint32_t aoff = (arr == 0) ? GA_H : (arr == 1) ? GA_L             \
                                : (arr == 2) ? GB_H : GB_L;                       \
                const char* src = (arr == 0) ? aHb : (arr == 1) ? aLb             \
                                 : (arr == 2) ? pHb : pLb;                        \
                uint32_t dst = sbase + aoff +                                     \
                    (uint32_t)(row * 128 + ((c ^ (row & 7)) << 4));               \
                cp16(dst, src + (size_t)row * 4096 + (size_t)(k0w) * 2 + c * 16); \
            }                                                                     \
        }                                                                         \
        CP_COMMIT();                                                              \
    }

    float acc[2][5][4];
    #pragma unroll
    for (int i = 0; i < 2; i++)
        #pragma unroll
        for (int j = 0; j < 5; j++)
            #pragma unroll
            for (int k = 0; k < 4; k++) acc[i][j][k] = 0.f;

    const int warpM = warp >> 1, warpN = warp & 1;
    const int rA = warpM * 32, nbase = warpN * 40;

    G_LOAD_STAGE(0, 0);

    for (int k = 0; k < 32; k++) {
        const int s = k & 1;
        if (k + 1 < 32) { G_LOAD_STAGE(s ^ 1, (k + 1) * 64); CP_WAIT1(); }
        else            { CP_WAIT0(); }
        __syncthreads();
        uint32_t base = sb + s * GM_STAGE;
        if (warpN == 0) mma_chunk<5>(base, nbase, rA, lane, acc);
        else            mma_chunk<4>(base, nbase, rA, lane, acc);
        __syncthreads();
    }

    // ---- fused combine epilogue: acc -> smem, then RoPE-weighted sum -> scores ----
    float* Gs = reinterpret_cast<float*>(dsm);   // [128][73] fp32, 37376 B
    const int NTe = warpN ? 4 : 5;
    for (int nt = 0; nt < NTe; nt++) {
        #pragma unroll
        for (int mt = 0; mt < 2; mt++) {
            int r = rA + mt * 16 + (lane >> 2);
            int n = nbase + nt * 8 + 2 * (lane & 3);
            float* g0 = Gs + r * 73 + n;
            g0[0] = acc[mt][nt][0];
            g0[1] = acc[mt][nt][1];
            g0[73 * 8] = acc[mt][nt][2];
            g0[73 * 8 + 1] = acc[mt][nt][3];
        }
    }
    __syncthreads();
    if (tid < 128) {
        const double INV2PI = 0.15915494309189535;
        const double TWOPI  = 6.283185307179586;
        int s = s0 + tid;
        const float* row = Gs + tid * 73;
        float accS = row[64] + pbCs[0];
        #pragma unroll 8
        for (int j = 0; j < 32; j++) {
            double ang = (double)s * finv[j];
            double kq = rint(ang * INV2PI);
            float r = (float)(ang - kq * TWOPI);
            float sn, cs;
            __sincosf(r, &sn, &cs);
            accS += cs * (row[j] + pbA[j]) + sn * (row[32 + j] + pbB[j]);
        }
        g_sc[(size_t)bh * Ss + s] = accS;
    }
}

// ---------------- softmax over s (per b,h) ----------------
__global__ __launch_bounds__(256) void softmax_kernel() {
    int row = blockIdx.x;
    float* pp = g_sc + (size_t)row * Ss;
    int tid = threadIdx.x;
    float v[8];
    float m = -1e30f;
    #pragma unroll
    for (int i = 0; i < 8; i++) { v[i] = pp[tid + i * 256]; m = fmaxf(m, v[i]); }
    #pragma unroll
    for (int o = 16; o; o >>= 1) m = fmaxf(m, __shfl_xor_sync(0xffffffffu, m, o));
    __shared__ float rs[8];
    int warp = tid >> 5, lane = tid & 31;
    if (lane == 0) rs[warp] = m;
    __syncthreads();
    float mm = rs[0];
    #pragma unroll
    for (int i = 1; i < 8; i++) mm = fmaxf(mm, rs[i]);
    float ssum = 0.f;
    #pragma unroll
    for (int i = 0; i < 8; i++) { v[i] = expf(v[i] - mm); ssum += v[i]; }
    #pragma unroll
    for (int o = 16; o; o >>= 1) ssum += __shfl_xor_sync(0xffffffffu, ssum, o);
    __syncthreads();
    if (lane == 0) rs[warp] = ssum;
    __syncthreads();
    float tot = 0.f;
    #pragma unroll
    for (int i = 0; i < 8; i++) tot += rs[i];
    float inv = 1.f / tot;
    #pragma unroll
    for (int i = 0; i < 8; i++) pp[tid + i * 256] = v[i] * inv;
}

// ---------------- c[b,h,e] = sum_s attn * hs ----------------
__global__ void zero_c_kernel() {
    int i = blockIdx.x * blockDim.x + threadIdx.x;
    if (i < Bb * Hh * Ee) g_c[i] = 0.f;
}

__global__ __launch_bounds__(128) void cvec_kernel() {
    __shared__ float at[16][128];
    int tid = threadIdx.x;
    int b = blockIdx.y;
    int e = blockIdx.x * 128 + tid;
    int sbase = blockIdx.z * 256;
    float acc[16];
    #pragma unroll
    for (int i = 0; i < 16; i++) acc[i] = 0.f;
    for (int sc = 0; sc < 256; sc += 128) {
        #pragma unroll
        for (int i = 0; i < 16; i++) {
            int idx = tid + i * 128;
            int hh = idx >> 7, si = idx & 127;
            at[hh][si] = g_sc[(size_t)(b * Hh + hh) * Ss + sbase + sc + si];
        }
        __syncthreads();
        size_t base = (size_t)(b * Ss + sbase + sc) * Ee + e;
        #pragma unroll 4
        for (int si = 0; si < 128; si++) {
            float x = __half2float(g_hsH[base + (size_t)si * Ee])
                    + __half2float(g_hsL[base + (size_t)si * Ee]);
            #pragma unroll
            for (int hh = 0; hh < 16; hh++) acc[hh] += at[hh][si] * x;
        }
        __syncthreads();
    }
    #pragma unroll
    for (int hh = 0; hh < 16; hh++)
        atomicAdd(&g_c[(size_t)(b * Hh + hh) * Ee + e], acc[hh]);
}

// ---------------- out_attn = c @ v_w.T (per head) + v_b ----------------
__global__ __launch_bounds__(256) void vproj_kernel(const float* __restrict__ vw,
                                                    const float* __restrict__ vb) {
    int b = blockIdx.y;
    int warp = threadIdx.x >> 5, lane = threadIdx.x & 31;
    int j = blockIdx.x * 8 + warp;
    int hh = j >> 7;
    const float4* crow = reinterpret_cast<const float4*>(g_c + (size_t)(b * Hh + hh) * Ee);
    const float4* wrow = reinterpret_cast<const float4*>(vw + (size_t)j * Ee);
    float acc = 0.f;
    #pragma unroll
    for (int it = 0; it < 16; it++) {
        int i4 = it * 32 + lane;
        float4 a = crow[i4], w = wrow[i4];
        acc += a.x * w.x + a.y * w.y + a.z * w.z + a.w * w.w;
    }
    #pragma unroll
    for (int o = 16; o; o >>= 1) acc += __shfl_xor_sync(0xffffffffu, acc, o);
    if (lane == 0) g_oattn[b * Ee + j] = acc + vb[j];
}

// ---------------- out = out_attn @ out_w.T + out_b ----------------
__global__ __launch_bounds__(256) void oproj_kernel(const float* __restrict__ ow,
                                                    const float* __restrict__ ob,
                                                    float* __restrict__ out) {
    int b = blockIdx.y;
    int warp = threadIdx.x >> 5, lane = threadIdx.x & 31;
    int j = blockIdx.x * 8 + warp;
    const float4* arow = reinterpret_cast<const float4*>(g_oattn + (size_t)b * Ee);
    const float4* wrow = reinterpret_cast<const float4*>(ow + (size_t)j * Ee);
    float acc = 0.f;
    #pragma unroll
    for (int it = 0; it < 16; it++) {
        int i4 = it * 32 + lane;
        float4 a = arow[i4], w = wrow[i4];
        acc += a.x * w.x + a.y * w.y + a.z * w.z + a.w * w.w;
    }
    #pragma unroll
    for (int o = 16; o; o >>= 1) acc += __shfl_xor_sync(0xffffffffu, acc, o);
    if (lane == 0) out[b * Ee + j] = acc + ob[j];
}

// ---------------- launch ----------------
extern "C" void kernel_launch(void* const* d_in, const int* in_sizes, int n_in,
                              void* d_out, int out_size) {
    const float* hs_in = (const float*)d_in[0];
    const int*   ids   = (const int*)d_in[1];
    const float* lnw = (const float*)d_in[2];
    const float* lnb = (const float*)d_in[3];
    const float* qw  = (const float*)d_in[4];
    const float* qb  = (const float*)d_in[5];
    const float* kw  = (const float*)d_in[6];
    const float* kb  = (const float*)d_in[7];
    const float* vw  = (const float*)d_in[8];
    const float* vb  = (const float*)d_in[9];
    const float* ow  = (const float*)d_in[10];
    const float* ob  = (const float*)d_in[11];
    float* out = (float*)d_out;

    cudaFuncSetAttribute(gemm_scores, cudaFuncAttributeMaxDynamicSharedMemorySize, GEMM_SMEM);

    ln_kernel<<<Bb * Ss, 256>>>(hs_in, lnw, lnb);
    ix_kernel<<<Bb, 256>>>(ids);
    q_kernel<<<dim3(Ee / 8, Bb), 256>>>(qw, qb);
    pmat_kernel<<<dim3(Ee / 256, Hh, Bb), 256>>>(kw);
    gemm_scores<<<dim3(Ss / 128, Bb * Hh), 256, GEMM_SMEM>>>(kb);
    softmax_kernel<<<Bb * Hh, 256>>>();
    zero_c_kernel<<<(Bb * Hh * Ee + 255) / 256, 256>>>();
    cvec_kernel<<<dim3(Ee / 128, Bb, 8), 128>>>();
    vproj_kernel<<<dim3(Ee / 8, Bb), 256>>>(vw, vb);
    oproj_kernel<<<dim3(Ee / 8, Bb), 256>>>(ow, ob, out);
}

// round 7
// speedup vs baseline: 1.7456x; 1.0061x over previous
#include <cuda_runtime.h>
#include <cuda_fp16.h>
#include <cstdint>
#include <math.h>

#define Bb 8
#define Ss 2048
#define Ee 2048
#define Hh 16
#define Dd 128
#define PADTOK 50257

// ---------------- scratch (device globals: allocation-free) ----------------
__device__ __half g_hsH[(size_t)Bb * Ss * Ee];      // hi fp16 split of LN output
__device__ __half g_hsL[(size_t)Bb * Ss * Ee];      // lo fp16 split
__device__ __half g_pH[(size_t)Bb * Hh * 64 * Ee];  // projected weights hi (cos/sin coeffs)
__device__ __half g_pL[(size_t)Bb * Hh * 64 * Ee];  // projected weights lo
__device__ float g_Cv[(size_t)Bb * Hh * Ee];        // C vector per (b,h), fp32
__device__ float g_q[Bb * Ee];
__device__ float g_sc[Bb * Hh * Ss];
__device__ float g_c[Bb * Hh * Ee];
__device__ float g_oattn[Bb * Ee];
__device__ int   g_ix[Bb];

// ---------------- helpers ----------------
__device__ __forceinline__ void splitp_h(float f0, float f1, uint32_t& hi, uint32_t& lo) {
    __half2 Hv = __floats2half2_rn(f0, f1);
    float r0 = f0 - __low2float(Hv);
    float r1 = f1 - __high2float(Hv);
    __half2 Lv = __floats2half2_rn(r0, r1);
    hi = *reinterpret_cast<uint32_t*>(&Hv);
    lo = *reinterpret_cast<uint32_t*>(&Lv);
}

__device__ __forceinline__ float h2sum(uint32_t h, uint32_t l, int sel) {
    __half2 hv = *reinterpret_cast<__half2*>(&h);
    __half2 lv = *reinterpret_cast<__half2*>(&l);
    return sel ? (__high2float(hv) + __high2float(lv))
               : (__low2float(hv) + __low2float(lv));
}

// ---------------- LayerNorm + fp16 hi/lo split ----------------
__global__ __launch_bounds__(256) void ln_kernel(const float* __restrict__ x,
                                                 const float* __restrict__ w,
                                                 const float* __restrict__ bias) {
    int row = blockIdx.x;
    const float4* xin = reinterpret_cast<const float4*>(x + (size_t)row * Ee);
    int tid = threadIdx.x;
    float4 v0 = xin[tid];
    float4 v1 = xin[tid + 256];
    float s  = v0.x + v0.y + v0.z + v0.w + v1.x + v1.y + v1.z + v1.w;
    float s2 = v0.x*v0.x + v0.y*v0.y + v0.z*v0.z + v0.w*v0.w
             + v1.x*v1.x + v1.y*v1.y + v1.z*v1.z + v1.w*v1.w;
    #pragma unroll
    for (int o = 16; o; o >>= 1) {
        s  += __shfl_xor_sync(0xffffffffu, s, o);
        s2 += __shfl_xor_sync(0xffffffffu, s2, o);
    }
    __shared__ float red[16];
    __shared__ float mv[2];
    int warp = tid >> 5, lane = tid & 31;
    if (lane == 0) { red[warp] = s; red[warp + 8] = s2; }
    __syncthreads();
    if (tid == 0) {
        float a = 0.f, b2 = 0.f;
        #pragma unroll
        for (int i = 0; i < 8; i++) { a += red[i]; b2 += red[i + 8]; }
        float mu  = a / (float)Ee;
        float var = b2 / (float)Ee - mu * mu;
        mv[0] = mu; mv[1] = rsqrtf(var + 1e-5f);
    }
    __syncthreads();
    float mu = mv[0], rs = mv[1];
    const float4* wv4 = reinterpret_cast<const float4*>(w);
    const float4* bv4 = reinterpret_cast<const float4*>(bias);
    uint2* outH = reinterpret_cast<uint2*>(g_hsH + (size_t)row * Ee);
    uint2* outL = reinterpret_cast<uint2*>(g_hsL + (size_t)row * Ee);
    {
        float4 wv = wv4[tid], bv = bv4[tid], o;
        o.x = (v0.x - mu) * rs * wv.x + bv.x;
        o.y = (v0.y - mu) * rs * wv.y + bv.y;
        o.z = (v0.z - mu) * rs * wv.z + bv.z;
        o.w = (v0.w - mu) * rs * wv.w + bv.w;
        uint32_t h0, l0, h1, l1;
        splitp_h(o.x, o.y, h0, l0); splitp_h(o.z, o.w, h1, l1);
        outH[tid] = make_uint2(h0, h1);
        outL[tid] = make_uint2(l0, l1);
    }
    {
        float4 wv = wv4[tid + 256], bv = bv4[tid + 256], o;
        o.x = (v1.x - mu) * rs * wv.x + bv.x;
        o.y = (v1.y - mu) * rs * wv.y + bv.y;
        o.z = (v1.z - mu) * rs * wv.z + bv.z;
        o.w = (v1.w - mu) * rs * wv.w + bv.w;
        uint32_t h0, l0, h1, l1;
        splitp_h(o.x, o.y, h0, l0); splitp_h(o.z, o.w, h1, l1);
        outH[tid + 256] = make_uint2(h0, h1);
        outL[tid + 256] = make_uint2(l0, l1);
    }
}

// ---------------- last non-pad index ----------------
__global__ __launch_bounds__(256) void ix_kernel(const int* __restrict__ ids) {
    int b = blockIdx.x;
    int m = -1;
    for (int s = threadIdx.x; s < Ss; s += 256)
        if (ids[b * Ss + s] != PADTOK) m = s;
    #pragma unroll
    for (int o = 16; o; o >>= 1) m = max(m, __shfl_xor_sync(0xffffffffu, m, o));
    __shared__ int rm[8];
    int warp = threadIdx.x >> 5, lane = threadIdx.x & 31;
    if (lane == 0) rm[warp] = m;
    __syncthreads();
    if (threadIdx.x == 0) {
        int mm = -1;
        #pragma unroll
        for (int i = 0; i < 8; i++) mm = max(mm, rm[i]);
        g_ix[b] = (mm < 0) ? 0 : mm;
    }
}

// ---------------- q = h_last @ q_w.T + q_b ----------------
__global__ __launch_bounds__(256) void q_kernel(const float* __restrict__ qw,
                                                const float* __restrict__ qb) {
    int b = blockIdx.y;
    int warp = threadIdx.x >> 5, lane = threadIdx.x & 31;
    int j = blockIdx.x * 8 + warp;
    size_t hb = ((size_t)(b * Ss) + g_ix[b]) * Ee;
    const uint2* hH = reinterpret_cast<const uint2*>(g_hsH + hb);
    const uint2* hL = reinterpret_cast<const uint2*>(g_hsL + hb);
    const float4* wrow = reinterpret_cast<const float4*>(qw + (size_t)j * Ee);
    float acc = 0.f;
    #pragma unroll
    for (int it = 0; it < 16; it++) {
        int i4 = it * 32 + lane;
        uint2 hv = hH[i4], lv = hL[i4];
        float4 w = wrow[i4];
        acc += h2sum(hv.x, lv.x, 0) * w.x;
        acc += h2sum(hv.x, lv.x, 1) * w.y;
        acc += h2sum(hv.y, lv.y, 0) * w.z;
        acc += h2sum(hv.y, lv.y, 1) * w.w;
    }
    #pragma unroll
    for (int o = 16; o; o >>= 1) acc += __shfl_xor_sync(0xffffffffu, acc, o);
    if (lane == 0) g_q[b * Ee + j] = acc + qb[j];
}

// ---------------- P matrices: fold q into k_w (RoPE projection) ----------------
// P[bh][n][e]: n<32: cos-coeff A_j; 32<=n<64: sin-coeff B_j.  C vector -> g_Cv (fp32).
__global__ __launch_bounds__(256) void pmat_kernel(const float* __restrict__ kw) {
    int tid = threadIdx.x;
    int e = blockIdx.x * 256 + tid;
    int h = blockIdx.y, b = blockIdx.z;
    __shared__ float qs[128];
    if (tid < 128) qs[tid] = g_q[b * Ee + h * Dd + tid];
    __syncthreads();
    size_t pbase = ((size_t)(b * Hh + h)) * 64 * Ee + e;
    const float* kwb = kw + (size_t)h * Dd * Ee + e;
    #pragma unroll 4
    for (int j = 0; j < 32; j++) {
        float k0 = kwb[(size_t)(2 * j) * Ee];
        float k1 = kwb[(size_t)(2 * j + 1) * Ee];
        float A  = k0 * qs[2 * j]     + k1 * qs[2 * j + 1];
        float Bv = k0 * qs[2 * j + 1] - k1 * qs[2 * j];
        __half ah = __float2half_rn(A);
        __half al = __float2half_rn(A - __half2float(ah));
        __half bh = __float2half_rn(Bv);
        __half bl = __float2half_rn(Bv - __half2float(bh));
        g_pH[pbase + (size_t)j * Ee] = ah;
        g_pL[pbase + (size_t)j * Ee] = al;
        g_pH[pbase + (size_t)(32 + j) * Ee] = bh;
        g_pL[pbase + (size_t)(32 + j) * Ee] = bl;
    }
    float C = 0.f;
    #pragma unroll 8
    for (int d = 64; d < 128; d++) C += kwb[(size_t)d * Ee] * qs[d];
    g_Cv[(size_t)(b * Hh + h) * Ee + e] = C;
}

// ---------------- GEMM G = hs @ P^T (3-term fp16 split, N=64) + in-reg C-dot ----
__device__ __forceinline__ void mma_f16(float c[4], uint32_t a0, uint32_t a1, uint32_t a2,
                                        uint32_t a3, uint32_t b0, uint32_t b1) {
    asm volatile(
        "mma.sync.aligned.m16n8k16.row.col.f32.f16.f16.f32 "
        "{%0,%1,%2,%3}, {%4,%5,%6,%7}, {%8,%9}, {%0,%1,%2,%3};"
        : "+f"(c[0]), "+f"(c[1]), "+f"(c[2]), "+f"(c[3])
        : "r"(a0), "r"(a1), "r"(a2), "r"(a3), "r"(b0), "r"(b1));
}

__device__ __forceinline__ void ldsm4(uint32_t r[4], uint32_t a) {
    asm volatile("ldmatrix.sync.aligned.m8n8.x4.shared.b16 {%0,%1,%2,%3}, [%4];"
                 : "=r"(r[0]), "=r"(r[1]), "=r"(r[2]), "=r"(r[3]) : "r"(a));
}

__device__ __forceinline__ void cp16(uint32_t dst, const void* src) {
    asm volatile("cp.async.cg.shared.global [%0], [%1], 16;" :: "r"(dst), "l"(src) : "memory");
}
#define CP_COMMIT() asm volatile("cp.async.commit_group;" ::: "memory")
#define CP_WAIT1()  asm volatile("cp.async.wait_group 1;" ::: "memory")
#define CP_WAIT0()  asm volatile("cp.async.wait_group 0;" ::: "memory")

// stage layout (byte offsets): A 128rowsx128B per limb, B 64rowsx128B per limb
#define GA_H 0
#define GA_L 16384
#define GB_H 32768
#define GB_L 40960
#define GM_STAGE 49152
#define GEMM_SMEM (2 * GM_STAGE)

__global__ void __launch_bounds__(256, 2) gemm_scores(const float* __restrict__ kb) {
    extern __shared__ char dsm[];
    __shared__ __align__(16) float pbA[32], pbB[32], pbCs[4];
    __shared__ __align__(16) double finv[32];
    __shared__ __align__(16) float Cs[2048];
    __shared__ __align__(16) float cred[128][2];

    const int tid = threadIdx.x, warp = tid >> 5, lane = tid & 31;
    const int bh = blockIdx.y, b = bh >> 4, h = bh & 15;
    const int s0 = blockIdx.x * 128;

    if (tid < 32) {
        finv[tid] = exp(-((double)(2 * tid) / 64.0) * 9.210340371976184);
        float q0 = g_q[b * Ee + h * Dd + 2 * tid];
        float q1 = g_q[b * Ee + h * Dd + 2 * tid + 1];
        float k0 = kb[h * Dd + 2 * tid];
        float k1 = kb[h * Dd + 2 * tid + 1];
        pbA[tid] = q0 * k0 + q1 * k1;
        pbB[tid] = q1 * k0 - q0 * k1;
    } else if (tid == 32) {
        float a = 0.f;
        for (int d = 64; d < 128; d++) a += kb[h * Dd + d] * g_q[b * Ee + h * Dd + d];
        pbCs[0] = a;
    }
    // C vector -> smem (fp32, 8KB)
    {
        const float4* cv = reinterpret_cast<const float4*>(g_Cv + (size_t)bh * Ee);
        #pragma unroll
        for (int i = 0; i < 2; i++) {
            float4 v = cv[tid + i * 256];
            *reinterpret_cast<float4*>(&Cs[(tid + i * 256) * 4]) = v;
        }
    }

    uint32_t sb;
    asm("{ .reg .u64 t; cvta.to.shared.u64 t, %1; cvt.u32.u64 %0, t; }" : "=r"(sb) : "l"(dsm));

    const char* aHb = (const char*)(g_hsH + (size_t)(b * Ss + s0) * Ee);
    const char* aLb = (const char*)(g_hsL + (size_t)(b * Ss + s0) * Ee);
    const char* pHb = (const char*)(g_pH + (size_t)bh * 64 * Ee);
    const char* pLb = (const char*)(g_pL + (size_t)bh * 64 * Ee);

// 3072 cp16 per stage: A_H 0..1023, A_L 1024..2047, B_H 2048..2559, B_L 2560..3071
#define G_LOAD_STAGE(st, k0w)                                                     \
    {                                                                             \
        uint32_t sbase = sb + (st) * GM_STAGE;                                    \
        _Pragma("unroll")                                                         \
        for (int i = 0; i < 12; i++) {                                            \
            int id = tid + 256 * i;                                               \
            int arr = (id < 1024) ? 0 : (id < 2048) ? 1 : (id < 2560) ? 2 : 3;    \
            int rid = id - ((arr == 0) ? 0 : (arr == 1) ? 1024                    \
                            : (arr == 2) ? 2048 : 2560);                          \
            int row = rid >> 3, c = rid & 7;                                      \
            uint32_t aoff = (arr == 0) ? GA_H : (arr == 1) ? GA_L                 \
                            : (arr == 2) ? GB_H : GB_L;                           \
            const char* src = (arr == 0) ? aHb : (arr == 1) ? aLb                 \
                             : (arr == 2) ? pHb : pLb;                            \
            uint32_t dst = sbase + aoff +                                         \
                (uint32_t)(row * 128 + ((c ^ (row & 7)) << 4));                   \
            cp16(dst, src + (size_t)row * 4096 + (size_t)(k0w) * 2 + c * 16);     \
        }                                                                         \
        CP_COMMIT();                                                              \
    }

    float acc[2][4][4];
    #pragma unroll
    for (int i = 0; i < 2; i++)
        #pragma unroll
        for (int j = 0; j < 4; j++)
            #pragma unroll
            for (int k = 0; k < 4; k++) acc[i][j][k] = 0.f;
    float cacc[2][2] = {{0.f, 0.f}, {0.f, 0.f}};

    const int warpM = warp >> 1, warpN = warp & 1;
    const int rA = warpM * 32, nbase = warpN * 32;
    const int g = lane >> 2, tq = lane & 3;

    G_LOAD_STAGE(0, 0);

    for (int k = 0; k < 32; k++) {
        const int s = k & 1;
        const int k0w = k * 64;
        if (k + 1 < 32) { G_LOAD_STAGE(s ^ 1, (k + 1) * 64); CP_WAIT1(); }
        else            { CP_WAIT0(); }
        __syncthreads();
        uint32_t base = sb + s * GM_STAGE;

        #pragma unroll
        for (int kk = 0; kk < 4; kk++) {
            const int kkc = kk * 2;
            uint32_t aH[2][4], aL[2][4];
            #pragma unroll
            for (int mt = 0; mt < 2; mt++) {
                int row = rA + mt * 16 + (lane & 15);
                int c16 = kkc + (lane >> 4);
                uint32_t off = (uint32_t)(row * 128 + ((c16 ^ (row & 7)) << 4));
                ldsm4(aH[mt], base + GA_H + off);
                ldsm4(aL[mt], base + GA_L + off);
            }
            uint32_t bH[8], bL[8];
            #pragma unroll
            for (int tp = 0; tp < 2; tp++) {
                int row = nbase + tp * 16 + ((lane >> 4) << 3) + (lane & 7);
                int c16 = kkc + ((lane >> 3) & 1);
                uint32_t off = (uint32_t)(row * 128 + ((c16 ^ (row & 7)) << 4));
                ldsm4(&bH[tp * 4], base + GB_H + off);
                ldsm4(&bL[tp * 4], base + GB_L + off);
            }
            // in-register C-dot on the fma pipe (wn0: kk 0-1, wn1: kk 2-3)
            if ((kk >> 1) == warpN) {
                #pragma unroll
                for (int mt = 0; mt < 2; mt++) {
                    #pragma unroll
                    for (int r = 0; r < 4; r++) {
                        float2 fh = __half22float2(*reinterpret_cast<__half2*>(&aH[mt][r]));
                        float2 fl = __half22float2(*reinterpret_cast<__half2*>(&aL[mt][r]));
                        int ki = k0w + kk * 16 + tq * 2 + ((r & 2) ? 8 : 0);
                        cacc[mt][r & 1] += (fh.x + fl.x) * Cs[ki] + (fh.y + fl.y) * Cs[ki + 1];
                    }
                }
            }
            #pragma unroll
            for (int nt = 0; nt < 4; nt++) {
                #pragma unroll
                for (int mt = 0; mt < 2; mt++) {
                    mma_f16(acc[mt][nt], aH[mt][0], aH[mt][1], aH[mt][2], aH[mt][3],
                            bH[nt * 2], bH[nt * 2 + 1]);
                    mma_f16(acc[mt][nt], aL[mt][0], aL[mt][1], aL[mt][2], aL[mt][3],
                            bH[nt * 2], bH[nt * 2 + 1]);
                    mma_f16(acc[mt][nt], aH[mt][0], aH[mt][1], aH[mt][2], aH[mt][3],
                            bL[nt * 2], bL[nt * 2 + 1]);
                }
            }
        }
        __syncthreads();
    }

    // reduce C-dot partials over the 4 tq lanes, stash per (row, wn)
    #pragma unroll
    for (int mt = 0; mt < 2; mt++) {
        #pragma unroll
        for (int rr = 0; rr < 2; rr++) {
            float p = cacc[mt][rr];
            p += __shfl_xor_sync(0xffffffffu, p, 1);
            p += __shfl_xor_sync(0xffffffffu, p, 2);
            if (tq == 0) cred[rA + mt * 16 + rr * 8 + g][warpN] = p;
        }
    }

    // acc -> smem G tile (stage-0 region of dsm; last chunk computed on stage 1)
    float* Gs = reinterpret_cast<float*>(dsm);   // [128][65]
    #pragma unroll
    for (int nt = 0; nt < 4; nt++) {
        #pragma unroll
        for (int mt = 0; mt < 2; mt++) {
            int r = rA + mt * 16 + (lane >> 2);
            int n = nbase + nt * 8 + 2 * (lane & 3);
            float* g0 = Gs + r * 65 + n;
            g0[0] = acc[mt][nt][0];
            g0[1] = acc[mt][nt][1];
            g0[65 * 8] = acc[mt][nt][2];
            g0[65 * 8 + 1] = acc[mt][nt][3];
        }
    }
    __syncthreads();
    if (tid < 128) {
        const double INV2PI = 0.15915494309189535;
        const double TWOPI  = 6.283185307179586;
        int s = s0 + tid;
        const float* row = Gs + tid * 65;
        float accS = cred[tid][0] + cred[tid][1] + pbCs[0];
        #pragma unroll 8
        for (int j = 0; j < 32; j++) {
            double ang = (double)s * finv[j];
            double kq = rint(ang * INV2PI);
            float r = (float)(ang - kq * TWOPI);
            float sn, cs;
            __sincosf(r, &sn, &cs);
            accS += cs * (row[j] + pbA[j]) + sn * (row[32 + j] + pbB[j]);
        }
        g_sc[(size_t)bh * Ss + s] = accS;
    }
}

// ---------------- softmax over s (per b,h) ----------------
__global__ __launch_bounds__(256) void softmax_kernel() {
    int row = blockIdx.x;
    float* pp = g_sc + (size_t)row * Ss;
    int tid = threadIdx.x;
    float v[8];
    float m = -1e30f;
    #pragma unroll
    for (int i = 0; i < 8; i++) { v[i] = pp[tid + i * 256]; m = fmaxf(m, v[i]); }
    #pragma unroll
    for (int o = 16; o; o >>= 1) m = fmaxf(m, __shfl_xor_sync(0xffffffffu, m, o));
    __shared__ float rs[8];
    int warp = tid >> 5, lane = tid & 31;
    if (lane == 0) rs[warp] = m;
    __syncthreads();
    float mm = rs[0];
    #pragma unroll
    for (int i = 1; i < 8; i++) mm = fmaxf(mm, rs[i]);
    float ssum = 0.f;
    #pragma unroll
    for (int i = 0; i < 8; i++) { v[i] = expf(v[i] - mm); ssum += v[i]; }
    #pragma unroll
    for (int o = 16; o; o >>= 1) ssum += __shfl_xor_sync(0xffffffffu, ssum, o);
    __syncthreads();
    if (lane == 0) rs[warp] = ssum;
    __syncthreads();
    float tot = 0.f;
    #pragma unroll
    for (int i = 0; i < 8; i++) tot += rs[i];
    float inv = 1.f / tot;
    #pragma unroll
    for (int i = 0; i < 8; i++) pp[tid + i * 256] = v[i] * inv;
}

// ---------------- c[b,h,e] = sum_s attn * hs ----------------
__global__ void zero_c_kernel() {
    int i = blockIdx.x * blockDim.x + threadIdx.x;
    if (i < Bb * Hh * Ee) g_c[i] = 0.f;
}

__global__ __launch_bounds__(128) void cvec_kernel() {
    __shared__ float at[16][128];
    int tid = threadIdx.x;
    int b = blockIdx.y;
    int e = blockIdx.x * 128 + tid;
    int sbase = blockIdx.z * 256;
    float acc[16];
    #pragma unroll
    for (int i = 0; i < 16; i++) acc[i] = 0.f;
    for (int sc = 0; sc < 256; sc += 128) {
        #pragma unroll
        for (int i = 0; i < 16; i++) {
            int idx = tid + i * 128;
            int hh = idx >> 7, si = idx & 127;
            at[hh][si] = g_sc[(size_t)(b * Hh + hh) * Ss + sbase + sc + si];
        }
        __syncthreads();
        size_t base = (size_t)(b * Ss + sbase + sc) * Ee + e;
        #pragma unroll 4
        for (int si = 0; si < 128; si++) {
            float x = __half2float(g_hsH[base + (size_t)si * Ee])
                    + __half2float(g_hsL[base + (size_t)si * Ee]);
            #pragma unroll
            for (int hh = 0; hh < 16; hh++) acc[hh] += at[hh][si] * x;
        }
        __syncthreads();
    }
    #pragma unroll
    for (int hh = 0; hh < 16; hh++)
        atomicAdd(&g_c[(size_t)(b * Hh + hh) * Ee + e], acc[hh]);
}

// ---------------- out_attn = c @ v_w.T (per head) + v_b ----------------
__global__ __launch_bounds__(256) void vproj_kernel(const float* __restrict__ vw,
                                                    const float* __restrict__ vb) {
    int b = blockIdx.y;
    int warp = threadIdx.x >> 5, lane = threadIdx.x & 31;
    int j = blockIdx.x * 8 + warp;
    int hh = j >> 7;
    const float4* crow = reinterpret_cast<const float4*>(g_c + (size_t)(b * Hh + hh) * Ee);
    const float4* wrow = reinterpret_cast<const float4*>(vw + (size_t)j * Ee);
    float acc = 0.f;
    #pragma unroll
    for (int it = 0; it < 16; it++) {
        int i4 = it * 32 + lane;
        float4 a = crow[i4], w = wrow[i4];
        acc += a.x * w.x + a.y * w.y + a.z * w.z + a.w * w.w;
    }
    #pragma unroll
    for (int o = 16; o; o >>= 1) acc += __shfl_xor_sync(0xffffffffu, acc, o);
    if (lane == 0) g_oattn[b * Ee + j] = acc + vb[j];
}

// ---------------- out = out_attn @ out_w.T + out_b ----------------
__global__ __launch_bounds__(256) void oproj_kernel(const float* __restrict__ ow,
                                                    const float* __restrict__ ob,
                                                    float* __restrict__ out) {
    int b = blockIdx.y;
    int warp = threadIdx.x >> 5, lane = threadIdx.x & 31;
    int j = blockIdx.x * 8 + warp;
    const float4* arow = reinterpret_cast<const float4*>(g_oattn + (size_t)b * Ee);
    const float4* wrow = reinterpret_cast<const float4*>(ow + (size_t)j * Ee);
    float acc = 0.f;
    #pragma unroll
    for (int it = 0; it < 16; it++) {
        int i4 = it * 32 + lane;
        float4 a = arow[i4], w = wrow[i4];
        acc += a.x * w.x + a.y * w.y + a.z * w.z + a.w * w.w;
    }
    #pragma unroll
    for (int o = 16; o; o >>= 1) acc += __shfl_xor_sync(0xffffffffu, acc, o);
    if (lane == 0) out[b * Ee + j] = acc + ob[j];
}

// ---------------- launch ----------------
extern "C" void kernel_launch(void* const* d_in, const int* in_sizes, int n_in,
                              void* d_out, int out_size) {
    const float* hs_in = (const float*)d_in[0];
    const int*   ids   = (const int*)d_in[1];
    const float* lnw = (const float*)d_in[2];
    const float* lnb = (const float*)d_in[3];
    const float* qw  = (const float*)d_in[4];
    const float* qb  = (const float*)d_in[5];
    const float* kw  = (const float*)d_in[6];
    const float* kb  = (const float*)d_in[7];
    const float* vw  = (const float*)d_in[8];
    const float* vb  = (const float*)d_in[9];
    const float* ow  = (const float*)d_in[10];
    const float* ob  = (const float*)d_in[11];
    float* out = (float*)d_out;

    cudaFuncSetAttribute(gemm_scores, cudaFuncAttributeMaxDynamicSharedMemorySize, GEMM_SMEM);

    ln_kernel<<<Bb * Ss, 256>>>(hs_in, lnw, lnb);
    ix_kernel<<<Bb, 256>>>(ids);
    q_kernel<<<dim3(Ee / 8, Bb), 256>>>(qw, qb);
    pmat_kernel<<<dim3(Ee / 256, Hh, Bb), 256>>>(kw);
    gemm_scores<<<dim3(Ss / 128, Bb * Hh), 256, GEMM_SMEM>>>(kb);
    softmax_kernel<<<Bb * Hh, 256>>>();
    zero_c_kernel<<<(Bb * Hh * Ee + 255) / 256, 256>>>();
    cvec_kernel<<<dim3(Ee / 128, Bb, 8), 128>>>();
    vproj_kernel<<<dim3(Ee / 8, Bb), 256>>>(vw, vb);
    oproj_kernel<<<dim3(Ee / 8, Bb), 256>>>(ow, ob, out);
}